// round 8
// baseline (speedup 1.0000x reference)
#include <cuda_runtime.h>
#include <cuda_fp16.h>
#include <cstdint>

#define IN_F   4096
#define OUT_F  11008
#define M_TOT  512
#define BM     128
#define BN     128
#define BK     128
#define NCHUNK (IN_F / BK)      // 32
#define NTHREADS 256
#define STAGE_BYTES 65536       // A 32KB + B 32KB
static constexpr int SMEM_BYTES = 2 * STAGE_BYTES;   // 128 KB

// x converted to fp16 once per launch (scratch: __device__ global, no allocs)
__device__ __align__(16) __half g_xh[M_TOT * IN_F];

// ---------------- helpers ----------------
__device__ __forceinline__ uint32_t smem_u32(const void* p) {
    uint32_t a;
    asm("{ .reg .u64 t; cvta.to.shared.u64 t, %1; cvt.u32.u64 %0, t; }" : "=r"(a) : "l"(p));
    return a;
}

#define LDSM4(r0, r1, r2, r3, addr) \
    asm volatile("ldmatrix.sync.aligned.m8n8.x4.shared.b16 {%0,%1,%2,%3}, [%4];" \
        : "=r"(r0), "=r"(r1), "=r"(r2), "=r"(r3) : "r"(addr))

#define MMA16816(c, a, b0, b1) \
    asm volatile("mma.sync.aligned.m16n8k16.row.col.f32.f16.f16.f32 " \
        "{%0,%1,%2,%3}, {%4,%5,%6,%7}, {%8,%9}, {%0,%1,%2,%3};" \
        : "+f"((c)[0]), "+f"((c)[1]), "+f"((c)[2]), "+f"((c)[3]) \
        : "r"((a)[0]), "r"((a)[1]), "r"((a)[2]), "r"((a)[3]), "r"(b0), "r"(b1))

#define CP_ASYNC16(dst, src) \
    asm volatile("cp.async.cg.shared.global [%0], [%1], 16;" :: "r"(dst), "l"(src) : "memory")
#define CP_ASYNC_COMMIT() asm volatile("cp.async.commit_group;" ::: "memory")
#define CP_ASYNC_WAIT0()  asm volatile("cp.async.wait_group 0;" ::: "memory")

__device__ __forceinline__ void sts128(uint32_t addr, uint4 v) {
    asm volatile("st.shared.v4.b32 [%0], {%1, %2, %3, %4};"
        :: "r"(addr), "r"(v.x), "r"(v.y), "r"(v.z), "r"(v.w) : "memory");
}

// dequant two int4-codes (stored as int32) -> packed fp16x2
__device__ __forceinline__ uint32_t packw(uint32_t q0, uint32_t q1, float s, float bz) {
    float f0 = fmaf((float)(int)q0, s, bz);
    float f1 = fmaf((float)(int)q1, s, bz);
    __half2 h = __floats2half2_rn(f0, f1);
    return *reinterpret_cast<uint32_t*>(&h);
}

#define SWZ(o) ((uint32_t)(o) ^ ((((uint32_t)(o)) >> 3) & 0x70))

// ---------------- kernel 1: x fp32 -> fp16 ----------------
__global__ void convert_x_kernel(const float* __restrict__ x) {
    int i = blockIdx.x * blockDim.x + threadIdx.x;
    float4 v = reinterpret_cast<const float4*>(x)[i];
    __half2 a = __floats2half2_rn(v.x, v.y);
    __half2 b = __floats2half2_rn(v.z, v.w);
    uint2 u;
    u.x = *reinterpret_cast<uint32_t*>(&a);
    u.y = *reinterpret_cast<uint32_t*>(&b);
    reinterpret_cast<uint2*>(g_xh)[i] = u;
}

// ---------------- kernel 2: dequant + HMMA GEMM ----------------
// Stage layout (per stage, 64KB):
//   A: 256 smem-rows x 128B at +0      (smem-row = khalf*128 + m-row, khalf = k>>6)
//   B: 256 smem-rows x 128B at +32768  (smem-row = khalf*128 + n-row)
__global__ __launch_bounds__(NTHREADS, 1)
void qlin_main_kernel(const int* __restrict__ qw,
                      const float* __restrict__ wsc,
                      const float* __restrict__ wzp,
                      const float* __restrict__ bias,
                      float* __restrict__ out) {
    extern __shared__ __align__(1024) char smem[];
    const uint32_t sb = smem_u32(smem);
    const int tid  = threadIdx.x;
    const int lane = tid & 31;
    const int wid  = tid >> 5;        // 8 warps
    const int mwarp = wid & 3;        // 4 M-warps (32 rows)
    const int nwarp = wid >> 2;       // 2 N-warps (64 cols)
    const int m0 = blockIdx.x * BM;   // 4 M-tiles (fast dim -> weight L2 reuse)
    const int n0 = blockIdx.y * BN;   // 86 N-tiles

    // ---- ldmatrix lane constants ----
    const int rA = lane & 15;
    const int cA = lane >> 4;
    const int rB = (lane & 7) | (((lane >> 4) & 1) << 3);
    const int cB = (lane >> 3) & 1;
    uint32_t baseA[2][2], baseB[4][2];   // [frag][khalf]
    #pragma unroll
    for (int i = 0; i < 2; ++i) {
        const int row = mwarp * 32 + i * 16 + rA;
        #pragma unroll
        for (int h = 0; h < 2; ++h)
            baseA[i][h] = (uint32_t)((h * 128 + row) * 128 + ((cA << 4) ^ ((row & 7) << 4)));
    }
    #pragma unroll
    for (int jj = 0; jj < 4; ++jj) {
        const int row = nwarp * 64 + jj * 16 + rB;
        #pragma unroll
        for (int h = 0; h < 2; ++h)
            baseB[jj][h] = (uint32_t)(32768 + (h * 128 + row) * 128 + ((cB << 4) ^ ((row & 7) << 4)));
    }

    // ---- A loader constants: 8 cp.async (16B) per thread per chunk ----
    uint32_t dstA[8];
    size_t   offA[8];
    #pragma unroll
    for (int t = 0; t < 8; ++t) {
        const int chunk = tid + t * NTHREADS;     // 0..2047
        const int smemrow = chunk >> 3;           // 0..255
        const int part = chunk & 7;
        const int r = smemrow & 127;
        const int khalf = smemrow >> 7;
        dstA[t] = SWZ((uint32_t)(smemrow * 128 + part * 16));
        offA[t] = (size_t)(m0 + r) * IN_F + khalf * 64 + part * 8;
    }

    // ---- B loader constants: 2 threads/row, 32 int32 per half per thread ----
    const int wrow  = tid >> 1;       // 0..127 (n-row)
    const int kpart = tid & 1;
    const int rowB  = n0 + wrow;
    const int* qrow = qw + (size_t)rowB * IN_F + kpart * 32;
    const uint32_t xorv = (uint32_t)((wrow & 7) << 4);

    float acc[2][8][4];
    #pragma unroll
    for (int i = 0; i < 2; ++i)
        #pragma unroll
        for (int j = 0; j < 8; ++j)
            #pragma unroll
            for (int c = 0; c < 4; ++c) acc[i][j][c] = 0.f;

    uint4 q[8];          // 32 staging regs (one K-half)
    float s_, bz_;

    auto loadB_h = [&](int kc, int h) {
        const int* p = qrow + kc * BK + h * 64;
        #pragma unroll
        for (int j = 0; j < 8; ++j)
            q[j] = *reinterpret_cast<const uint4*>(p + j * 4);
        if (h == 0) {
            const float s = wsc[rowB * 32 + kc];   // group size 128 == BK
            s_ = s;
            bz_ = -wzp[rowB * 32 + kc] * s;
        }
    };

    auto convertB_h = [&](uint32_t stage, int h) {
        const uint32_t rbase = 32768u + (uint32_t)((h * 128 + wrow) * 128);
        #pragma unroll
        for (int j = 0; j < 4; ++j) {
            uint4 hh;
            hh.x = packw(q[2 * j].x, q[2 * j].y, s_, bz_);
            hh.y = packw(q[2 * j].z, q[2 * j].w, s_, bz_);
            hh.z = packw(q[2 * j + 1].x, q[2 * j + 1].y, s_, bz_);
            hh.w = packw(q[2 * j + 1].z, q[2 * j + 1].w, s_, bz_);
            const uint32_t off = (uint32_t)(kpart * 64 + j * 16) ^ xorv;
            sts128(stage + rbase + off, hh);
        }
    };

    auto cpasyncA = [&](int kc, uint32_t stage) {
        #pragma unroll
        for (int t = 0; t < 8; ++t)
            CP_ASYNC16(stage + dstA[t], g_xh + offA[t] + (size_t)kc * BK);
        CP_ASYNC_COMMIT();
    };

    auto mmaHalf = [&](uint32_t stage, int h) {
        #pragma unroll
        for (int ks = 0; ks < 4; ++ks) {
            const uint32_t ax = (uint32_t)(ks << 5);
            uint32_t a[2][4];
            LDSM4(a[0][0], a[0][1], a[0][2], a[0][3], (stage + baseA[0][h]) ^ ax);
            LDSM4(a[1][0], a[1][1], a[1][2], a[1][3], (stage + baseA[1][h]) ^ ax);
            uint32_t bf[8][2];
            #pragma unroll
            for (int jj = 0; jj < 4; ++jj) {
                uint32_t r0, r1, r2, r3;
                LDSM4(r0, r1, r2, r3, (stage + baseB[jj][h]) ^ ax);
                bf[2 * jj][0] = r0;      bf[2 * jj][1] = r1;
                bf[2 * jj + 1][0] = r2;  bf[2 * jj + 1][1] = r3;
            }
            #pragma unroll
            for (int i = 0; i < 2; ++i)
                #pragma unroll
                for (int j = 0; j < 8; ++j)
                    MMA16816(acc[i][j], a[i], bf[j][0], bf[j][1]);
        }
    };

    // ---- prologue: chunk 0 into stage 0 ----
    const uint32_t st0 = sb;
    cpasyncA(0, st0);
    loadB_h(0, 0); convertB_h(st0, 0);
    loadB_h(0, 1); convertB_h(st0, 1);
    CP_ASYNC_WAIT0();
    __syncthreads();

    // ---- main loop: 2-stage, weights split in K-halves ----
    for (int kc = 0; kc < NCHUNK; ++kc) {
        const uint32_t cur = sb + (uint32_t)((kc & 1) << 16);
        const uint32_t nxt = sb + (uint32_t)(((kc + 1) & 1) << 16);
        const bool more = (kc + 1 < NCHUNK);
        if (more) { cpasyncA(kc + 1, nxt); loadB_h(kc + 1, 0); }
        mmaHalf(cur, 0);
        if (more) { convertB_h(nxt, 0); loadB_h(kc + 1, 1); }
        mmaHalf(cur, 1);
        if (more) { convertB_h(nxt, 1); }
        CP_ASYNC_WAIT0();
        __syncthreads();
    }

    // ---- epilogue: direct float2 stores + bias ----
    const int r_base = m0 + mwarp * 32 + (lane >> 2);
    #pragma unroll
    for (int j = 0; j < 8; ++j) {
        const int col = n0 + nwarp * 64 + j * 8 + (lane & 3) * 2;
        const float2 bv = *reinterpret_cast<const float2*>(&bias[col]);
        #pragma unroll
        for (int i = 0; i < 2; ++i) {
            const int r0 = r_base + i * 16;
            float2 v0 = make_float2(acc[i][j][0] + bv.x, acc[i][j][1] + bv.y);
            float2 v1 = make_float2(acc[i][j][2] + bv.x, acc[i][j][3] + bv.y);
            *reinterpret_cast<float2*>(&out[(size_t)r0 * OUT_F + col]) = v0;
            *reinterpret_cast<float2*>(&out[(size_t)(r0 + 8) * OUT_F + col]) = v1;
        }
    }
}

// ---------------- launch ----------------
extern "C" void kernel_launch(void* const* d_in, const int* in_sizes, int n_in,
                              void* d_out, int out_size) {
    (void)in_sizes; (void)n_in; (void)out_size;
    const float* x    = (const float*)d_in[0];
    const int*   qw   = (const int*)d_in[1];
    const float* wsc  = (const float*)d_in[2];
    const float* wzp  = (const float*)d_in[3];
    const float* bias = (const float*)d_in[4];
    float* out = (float*)d_out;

    cudaFuncSetAttribute(qlin_main_kernel,
                         cudaFuncAttributeMaxDynamicSharedMemorySize, SMEM_BYTES);

    convert_x_kernel<<<2048, 256>>>(x);
    qlin_main_kernel<<<dim3(4, 86), NTHREADS, SMEM_BYTES>>>(qw, wsc, wzp, bias, out);
}

// round 9
// speedup vs baseline: 1.6302x; 1.6302x over previous
#include <cuda_runtime.h>
#include <cuda_fp16.h>
#include <cstdint>

#define IN_F   4096
#define OUT_F  11008
#define M_TOT  512
#define BM     128
#define BN     128
#define BK     64
#define NCHUNK (IN_F / BK)      // 64
#define NTHREADS 256

// x converted to fp16 once per launch (scratch: __device__ global, no allocs)
__device__ __align__(16) __half g_xh[M_TOT * IN_F];

// ---------------- helpers ----------------
__device__ __forceinline__ uint32_t smem_u32(const void* p) {
    uint32_t a;
    asm("{ .reg .u64 t; cvta.to.shared.u64 t, %1; cvt.u32.u64 %0, t; }" : "=r"(a) : "l"(p));
    return a;
}

#define LDSM4(r0, r1, r2, r3, addr) \
    asm volatile("ldmatrix.sync.aligned.m8n8.x4.shared.b16 {%0,%1,%2,%3}, [%4];" \
        : "=r"(r0), "=r"(r1), "=r"(r2), "=r"(r3) : "r"(addr))

#define MMA16816(c, a, b0, b1) \
    asm volatile("mma.sync.aligned.m16n8k16.row.col.f32.f16.f16.f32 " \
        "{%0,%1,%2,%3}, {%4,%5,%6,%7}, {%8,%9}, {%0,%1,%2,%3};" \
        : "+f"((c)[0]), "+f"((c)[1]), "+f"((c)[2]), "+f"((c)[3]) \
        : "r"((a)[0]), "r"((a)[1]), "r"((a)[2]), "r"((a)[3]), "r"(b0), "r"(b1))

#define CP_ASYNC16(dst, src) \
    asm volatile("cp.async.cg.shared.global [%0], [%1], 16;" :: "r"(dst), "l"(src) : "memory")
#define CP_ASYNC_COMMIT() asm volatile("cp.async.commit_group;" ::: "memory")
#define CP_ASYNC_WAIT0()  asm volatile("cp.async.wait_group 0;" ::: "memory")

__device__ __forceinline__ void sts128(uint32_t addr, uint4 v) {
    asm volatile("st.shared.v4.b32 [%0], {%1, %2, %3, %4};"
        :: "r"(addr), "r"(v.x), "r"(v.y), "r"(v.z), "r"(v.w) : "memory");
}

// dequant two int4-codes (stored as int32) -> packed fp16x2
__device__ __forceinline__ uint32_t packw(uint32_t q0, uint32_t q1, float s, float bz) {
    float f0 = fmaf((float)(int)q0, s, bz);
    float f1 = fmaf((float)(int)q1, s, bz);
    __half2 h = __floats2half2_rn(f0, f1);
    return *reinterpret_cast<uint32_t*>(&h);
}

#define SWZ(o) ((uint32_t)(o) ^ ((((uint32_t)(o)) >> 3) & 0x70))

// ---------------- kernel 1: x fp32 -> fp16 ----------------
__global__ void convert_x_kernel(const float* __restrict__ x) {
    int i = blockIdx.x * blockDim.x + threadIdx.x;   // 524288 threads, 4 elems each
    float4 v = reinterpret_cast<const float4*>(x)[i];
    __half2 a = __floats2half2_rn(v.x, v.y);
    __half2 b = __floats2half2_rn(v.z, v.w);
    uint2 u;
    u.x = *reinterpret_cast<uint32_t*>(&a);
    u.y = *reinterpret_cast<uint32_t*>(&b);
    reinterpret_cast<uint2*>(g_xh)[i] = u;
}

// ---------------- kernel 2: dequant + HMMA GEMM ----------------
// Dynamic smem: stage s (s=0,1) at s*32768:
//   A tile: 128 rows x 64 fp16 (128B/row, SW128)  -> offset 0     (16 KB)
//   B tile: 128 rows x 64 fp16 (128B/row, SW128)  -> offset 16384 (16 KB)
static constexpr int SMEM_BYTES = 2 * 32768;   // 64 KB  (x2 CTAs = 128 KB/SM)

__global__ __launch_bounds__(NTHREADS, 2)
void qlin_main_kernel(const int* __restrict__ qw,
                      const float* __restrict__ wsc,
                      const float* __restrict__ wzp,
                      const float* __restrict__ bias,
                      float* __restrict__ out) {
    extern __shared__ __align__(1024) char smem[];
    const uint32_t sb = smem_u32(smem);
    const int tid  = threadIdx.x;
    const int lane = tid & 31;
    const int wid  = tid >> 5;
    const int mwarp = wid & 3;        // 4 M-warps
    const int nwarp = wid >> 2;       // 2 N-warps
    const int m0 = blockIdx.x * BM;   // 4 M-tiles (fast dim -> weight L2 reuse)
    const int n0 = blockIdx.y * BN;   // 86 N-tiles

    // ---- ldmatrix lane constants (SW128: addr = base ^ (ks<<5)) ----
    const int rA = lane & 15;
    const int cA = lane >> 4;                       // 0/1 (k halves)
    const int rB = (lane & 7) | (((lane >> 4) & 1) << 3);
    const int cB = (lane >> 3) & 1;
    uint32_t baseA[2], baseB[4];
    #pragma unroll
    for (int i = 0; i < 2; ++i) {
        const int row = mwarp * 32 + i * 16 + rA;
        baseA[i] = (uint32_t)(row * 128 + ((cA << 4) ^ ((row & 7) << 4)));
    }
    #pragma unroll
    for (int jj = 0; jj < 4; ++jj) {
        const int row = nwarp * 64 + jj * 16 + rB;
        baseB[jj] = (uint32_t)(16384 + row * 128 + ((cB << 4) ^ ((row & 7) << 4)));
    }

    // ---- loader lane constants: row = wrow + t*32, k-part = kpart ----
    const int wrow  = tid >> 3;       // 0..31
    const int kpart = tid & 7;        // 8 threads per row
    uint32_t dstA[4], dstB[4];
    #pragma unroll
    for (int t = 0; t < 4; ++t) {
        const int row = wrow + t * 32;
        const uint32_t sw = (uint32_t)((kpart << 4) ^ ((row & 7) << 4));
        dstA[t] = (uint32_t)(row * 128) + sw;
        dstB[t] = 16384u + (uint32_t)(row * 128) + sw;
    }

    float acc[2][8][4];
    #pragma unroll
    for (int i = 0; i < 2; ++i)
        #pragma unroll
        for (int j = 0; j < 8; ++j)
            #pragma unroll
            for (int c = 0; c < 4; ++c) acc[i][j][c] = 0.f;

    uint4 qa[2], qb[2];       // 16 staging regs (one half = rows t, t+1)
    float s_[4], bz_[4];      // per-t scales, persist across a kc pair

    // B weight LDG (int32 codes) for half h (t = 2h, 2h+1)
    auto loadB_h = [&](int kc, int h) {
        #pragma unroll
        for (int t = 0; t < 2; ++t) {
            const int tt = 2 * h + t;
            const int row = n0 + wrow + tt * 32;
            const int* p = qw + (size_t)row * IN_F + kc * BK + kpart * 8;
            qa[t] = *reinterpret_cast<const uint4*>(p);
            qb[t] = *reinterpret_cast<const uint4*>(p + 4);
            if ((kc & 1) == 0) {
                const int g = kc >> 1;
                const float s = wsc[row * 32 + g];
                s_[tt] = s;
                bz_[tt] = -wzp[row * 32 + g] * s;
            }
        }
    };

    auto convertB_h = [&](uint32_t stage, int h) {
        #pragma unroll
        for (int t = 0; t < 2; ++t) {
            const int tt = 2 * h + t;
            uint4 hh;
            hh.x = packw(qa[t].x, qa[t].y, s_[tt], bz_[tt]);
            hh.y = packw(qa[t].z, qa[t].w, s_[tt], bz_[tt]);
            hh.z = packw(qb[t].x, qb[t].y, s_[tt], bz_[tt]);
            hh.w = packw(qb[t].z, qb[t].w, s_[tt], bz_[tt]);
            sts128(stage + dstB[tt], hh);
        }
    };

    auto cpasyncA = [&](int kc, uint32_t stage) {
        #pragma unroll
        for (int t = 0; t < 4; ++t) {
            const int row = wrow + t * 32;
            const __half* src = g_xh + (size_t)(m0 + row) * IN_F + kc * BK + kpart * 8;
            CP_ASYNC16(stage + dstA[t], src);
        }
        CP_ASYNC_COMMIT();
    };

    // two ks-steps of MMA (ks = k0, k0+1)
    auto mmaSteps = [&](uint32_t stage, int k0) {
        #pragma unroll
        for (int ks = k0; ks < k0 + 2; ++ks) {
            const uint32_t ax = (uint32_t)(ks << 5);
            uint32_t a[2][4];
            LDSM4(a[0][0], a[0][1], a[0][2], a[0][3], (stage + baseA[0]) ^ ax);
            LDSM4(a[1][0], a[1][1], a[1][2], a[1][3], (stage + baseA[1]) ^ ax);
            uint32_t bf[8][2];
            #pragma unroll
            for (int jj = 0; jj < 4; ++jj) {
                uint32_t r0, r1, r2, r3;
                LDSM4(r0, r1, r2, r3, (stage + baseB[jj]) ^ ax);
                bf[2 * jj][0] = r0;      bf[2 * jj][1] = r1;
                bf[2 * jj + 1][0] = r2;  bf[2 * jj + 1][1] = r3;
            }
            #pragma unroll
            for (int i = 0; i < 2; ++i)
                #pragma unroll
                for (int j = 0; j < 8; ++j)
                    MMA16816(acc[i][j], a[i], bf[j][0], bf[j][1]);
        }
    };

    // ---- prologue: chunk 0 into stage 0 ----
    loadB_h(0, 0);
    cpasyncA(0, sb);
    convertB_h(sb, 0);
    loadB_h(0, 1);
    convertB_h(sb, 1);
    CP_ASYNC_WAIT0();
    __syncthreads();

    // ---- main loop (double buffered; B load/convert split around MMA halves) ----
    for (int kc = 0; kc < NCHUNK; ++kc) {
        const uint32_t cur = sb + (uint32_t)((kc & 1) << 15);
        const uint32_t nxt = sb + (uint32_t)(((kc + 1) & 1) << 15);
        const bool more = (kc + 1 < NCHUNK);
        if (more) {
            loadB_h(kc + 1, 0);       // 16-reg LDG batch, lands under ks0-1
            cpasyncA(kc + 1, nxt);
        }
        mmaSteps(cur, 0);
        if (more) {
            convertB_h(nxt, 0);
            loadB_h(kc + 1, 1);       // second batch, lands under ks2-3
        }
        mmaSteps(cur, 2);
        if (more) {
            convertB_h(nxt, 1);
            CP_ASYNC_WAIT0();
        }
        __syncthreads();
    }

    // ---- epilogue: direct float2 stores + bias ----
    const int r_base = m0 + mwarp * 32 + (lane >> 2);
    #pragma unroll
    for (int j = 0; j < 8; ++j) {
        const int col = n0 + nwarp * 64 + j * 8 + (lane & 3) * 2;
        const float2 bv = *reinterpret_cast<const float2*>(&bias[col]);
        #pragma unroll
        for (int i = 0; i < 2; ++i) {
            const int r0 = r_base + i * 16;
            float2 v0 = make_float2(acc[i][j][0] + bv.x, acc[i][j][1] + bv.y);
            float2 v1 = make_float2(acc[i][j][2] + bv.x, acc[i][j][3] + bv.y);
            *reinterpret_cast<float2*>(&out[(size_t)r0 * OUT_F + col]) = v0;
            *reinterpret_cast<float2*>(&out[(size_t)(r0 + 8) * OUT_F + col]) = v1;
        }
    }
}

// ---------------- launch ----------------
extern "C" void kernel_launch(void* const* d_in, const int* in_sizes, int n_in,
                              void* d_out, int out_size) {
    (void)in_sizes; (void)n_in; (void)out_size;
    const float* x    = (const float*)d_in[0];
    const int*   qw   = (const int*)d_in[1];
    const float* wsc  = (const float*)d_in[2];
    const float* wzp  = (const float*)d_in[3];
    const float* bias = (const float*)d_in[4];
    float* out = (float*)d_out;

    cudaFuncSetAttribute(qlin_main_kernel,
                         cudaFuncAttributeMaxDynamicSharedMemorySize, SMEM_BYTES);

    convert_x_kernel<<<2048, 256>>>(x);
    qlin_main_kernel<<<dim3(4, 86), NTHREADS, SMEM_BYTES>>>(qw, wsc, wzp, bias, out);
}